// round 3
// baseline (speedup 1.0000x reference)
#include <cuda_runtime.h>
#include <cstdint>

#define TBLOCK  256
#define ITEMS   8
#define NFILT   11
#define NCOLS   262144
#define NROWS   128
#define TILE    (TBLOCK * ITEMS)      // 2048 outputs per block
#define HALO_L  8                      // staged left apron (need 5)
#define SWIDTH  2064                   // complexes staged: cols [tile0-8, tile0+2056)
#define SBYTES  (SWIDTH * 8)           // 16512 bytes, 16B multiple

typedef unsigned long long u64;

__device__ __forceinline__ u64 pack2(float lo, float hi) {
    u64 r;
    asm("mov.b64 %0, {%1, %2};" : "=l"(r) : "f"(lo), "f"(hi));
    return r;
}
__device__ __forceinline__ void unpack2(u64 v, float& lo, float& hi) {
    asm("mov.b64 {%0, %1}, %2;" : "=f"(lo), "=f"(hi) : "l"(v));
}
__device__ __forceinline__ u64 fma2(u64 a, u64 b, u64 c) {
    u64 d;
    asm("fma.rn.f32x2 %0, %1, %2, %3;" : "=l"(d) : "l"(a), "l"(b), "l"(c));
    return d;
}
__device__ __forceinline__ uint32_t smem_u32(const void* p) {
    return (uint32_t)__cvta_generic_to_shared(p);
}

__global__ void __launch_bounds__(TBLOCK) fir_complex_tma_kernel(
    const float2* __restrict__ X, const float* __restrict__ phi,
    float2* __restrict__ Y)
{
    __shared__ __align__(16) float2 sx[SWIDTH];
    __shared__ __align__(8)  u64    mbar;

    const int tid   = threadIdx.x;
    const int row   = blockIdx.y;
    const int tile0 = blockIdx.x * TILE;
    const float2* __restrict__ xrow = X + (size_t)row * NCOLS;
    float2* __restrict__ yrow       = Y + (size_t)row * NCOLS;

    const bool interior = (tile0 >= HALO_L) && (tile0 - HALO_L + SWIDTH <= NCOLS);

    if (interior) {
        // TMA bulk staging: L2 -> SMEM, bypassing L1/registers entirely.
        if (tid == 0) {
            uint32_t mb = smem_u32(&mbar);
            uint32_t sd = smem_u32(sx);
            const void* gsrc = (const void*)(xrow + (tile0 - HALO_L));
            asm volatile("mbarrier.init.shared::cta.b64 [%0], 1;" :: "r"(mb));
            asm volatile("fence.proxy.async.shared::cta;" ::: "memory");
            asm volatile("mbarrier.arrive.expect_tx.shared::cta.b64 _, [%0], %1;"
                         :: "r"(mb), "r"((uint32_t)SBYTES));
            asm volatile(
                "cp.async.bulk.shared::cta.global.mbarrier::complete_tx::bytes "
                "[%0], [%1], %2, [%3];"
                :: "r"(sd), "l"(gsrc), "r"((uint32_t)SBYTES), "r"(mb) : "memory");
        }
        __syncthreads();   // init happens-before every thread's wait
        {
            uint32_t mb = smem_u32(&mbar);
            uint32_t done;
            asm volatile(
                "{\n\t.reg .pred p;\n\t"
                "mbarrier.try_wait.parity.acquire.cta.shared::cta.b64 p, [%1], 0;\n\t"
                "selp.b32 %0, 1, 0, p;\n\t}"
                : "=r"(done) : "r"(mb) : "memory");
            if (!done) {
                asm volatile(
                    "{\n\t.reg .pred P1;\n\t"
                    "W_%=:\n\t"
                    "mbarrier.try_wait.parity.acquire.cta.shared::cta.b64 P1, [%0], 0, 0x989680;\n\t"
                    "@P1 bra.uni D_%=;\n\t"
                    "bra.uni W_%=;\n\t"
                    "D_%=:\n\t}"
                    :: "r"(mb) : "memory");
            }
        }
    } else {
        // Row-edge blocks (2 of 128 per row): bounds-checked scalar staging.
        for (int j = tid; j < SWIDTH; j += TBLOCK) {
            int g = tile0 - HALO_L + j;
            sx[j] = (g >= 0 && g < NCOLS) ? xrow[g] : make_float2(0.f, 0.f);
        }
        __syncthreads();
    }

    // Coefficients A[k] = (wr_k, wi_k) — phi's native layout.
    u64 A[NFILT];
#pragma unroll
    for (int k = 0; k < NFILT; k++) {
        float2 w = __ldg(((const float2*)phi) + k);
        A[k] = pack2(w.x, w.y);
    }

    // P[i] = sum_k xr*(wr,wi);  Q[i] = sum_k xi*(wr,wi)
    // out_i uses local complex j = 8*tid + i + k + 3  (col = tile0 - 8 + j)
    u64 P[ITEMS], Q[ITEMS];
#pragma unroll
    for (int i = 0; i < ITEMS; i++) { P[i] = 0ull; Q[i] = 0ull; }

    const float4* win = (const float4*)sx;   // chunk q holds complexes {2q, 2q+1} rel. to 8*tid
#pragma unroll
    for (int q = 1; q <= 10; q++) {
        float4 v = win[4 * tid + q];
#pragma unroll
        for (int h = 0; h < 2; h++) {
            const int r  = 2 * q + h;              // relative complex index, 2..21
            const float re = h ? v.z : v.x;
            const float im = h ? v.w : v.y;
            u64 xrr = pack2(re, re);
            u64 xii = pack2(im, im);
#pragma unroll
            for (int i = 0; i < ITEMS; i++) {
                const int k = r - 3 - i;           // compile-time after unroll
                if (k >= 0 && k < NFILT) {
                    P[i] = fma2(xrr, A[k], P[i]);
                    Q[i] = fma2(xii, A[k], Q[i]);
                }
            }
        }
    }

    // out = (P.lo - Q.hi, P.hi + Q.lo)
    const int c0 = tile0 + ITEMS * tid;
    float4 o[ITEMS / 2];
#pragma unroll
    for (int i = 0; i < ITEMS; i++) {
        float prr, pri, qir, qii;
        unpack2(P[i], prr, pri);
        unpack2(Q[i], qir, qii);
        float ore = prr - qii;
        float oim = pri + qir;
        if (i & 1) { o[i / 2].z = ore; o[i / 2].w = oim; }
        else       { o[i / 2].x = ore; o[i / 2].y = oim; }
    }
    float4* yo = (float4*)(yrow + c0);
#pragma unroll
    for (int q = 0; q < ITEMS / 2; q++) yo[q] = o[q];
}

extern "C" void kernel_launch(void* const* d_in, const int* in_sizes, int n_in,
                              void* d_out, int out_size)
{
    const float2* X   = (const float2*)d_in[0];
    const float*  phi = (const float*)d_in[1];
    float2*       Y   = (float2*)d_out;

    dim3 grid(NCOLS / TILE, NROWS);
    fir_complex_tma_kernel<<<grid, TBLOCK>>>(X, phi, Y);
}